// round 13
// baseline (speedup 1.0000x reference)
#include <cuda_runtime.h>

#define S_DIM 8192
#define CIN   32
#define COUT  8
#define BATCH 128
#define TS    64          // s positions per block (kernel 2)
#define NBSPLIT 16        // batch splits: 2048 blocks = 6.9 waves (tail ~8%);
                          // extra w2 re-reads are L2-resident (8.4 MB)
#define BPB   (BATCH / NBSPLIT)
#define HPAD  36          // padded row stride for transposed h tile (floats)

static_assert(BPB >= 2, "distance-2 circular prefetch preloads 2 batches");
static_assert(BATCH % NBSPLIT == 0, "clean batch split");

// 1 MB scratch for w1sum[j][s] = sum_i w1[i][j][s]
__device__ float g_w1sum[CIN * S_DIM];

__device__ __forceinline__ float tanh_fast(float x) {
    float y;
    asm("tanh.approx.f32 %0, %1;" : "=f"(y) : "f"(x));
    return y;
}

// ---------------------------------------------------------------------------
// Kernel 1: w1sum[j,s] = sum_i w1[i,j,s].  float4-vectorized, fully coalesced,
// 32 independent loads per thread (high MLP). w1 is read ONCE -> streaming
// (__ldcs, evict-first) so it never displaces useful L2 lines.
// ---------------------------------------------------------------------------
__global__ void w1sum_kernel(const float* __restrict__ w1) {
    int t = blockIdx.x * blockDim.x + threadIdx.x;   // over CIN*S/4 float4s
    const float4* w14 = (const float4*)w1;
    float4 acc = make_float4(0.f, 0.f, 0.f, 0.f);
#pragma unroll
    for (int i = 0; i < CIN; ++i) {
        float4 v = __ldcs(&w14[(size_t)i * (CIN * S_DIM / 4) + t]);
        acc.x += v.x; acc.y += v.y; acc.z += v.z; acc.w += v.w;
    }
    ((float4*)g_w1sum)[t] = acc;
}

// ---------------------------------------------------------------------------
// Kernel 2: fused stage1 (tanh scale) + stage2 (per-s 32->8 contraction) + tanh
//
// Block: 256 threads. Grid: (S/TS, NBSPLIT) = (128, 16) = 2048 blocks.
// Phase A (per batch): thread (jg 0..7, ss 0..31) computes h for
//   j = 4jg..4jg+3 at s = ss and ss+32 from prefetched x registers (streaming
//   __ldcs) and stores two float4s into the transposed, padded h tile
//   (conflict-free STS.128: banks 4*ss+jg4 cover all 32 per quarter-phase).
//   Double-buffered on batch parity: ONE barrier per iteration.
// Phase B (per batch): thread (op 0..3, sl 0..63) reads h[sl][:] as
//   8x LDS.128 (conflict-free: banks 4*sl+4g) and contracts against a
//   64-register w2 tile (2 output channels per thread); accurate tanhf +
//   streaming __stcs store.
// x prefetch is DISTANCE-2 circular (slot = bi & 1): consumed in phase A of
//   batch b, immediately re-issued for batch b+2. Loop is FULLY UNROLLED
//   (BPB = 8), so the prefetch guard (bi + 2 < BPB) folds at COMPILE TIME:
//   the last two iterations emit no prefetch LDGs at all (no clamp, no SEL,
//   no redundant loads). Incremental base pointers keep live registers
//   minimal across the barrier (guards the 128-reg occ-2 cap).
// ---------------------------------------------------------------------------
__global__ __launch_bounds__(256, 2)
void fused_kernel(const float* __restrict__ x,
                  const float* __restrict__ w2,
                  const float* __restrict__ bias,
                  float* __restrict__ out) {
    __shared__ float w1s[CIN][TS];             // stage-1 weights, [j][s]
    __shared__ float hsh[2][TS][HPAD];         // DOUBLE-BUFFERED h tile [s][j]

    const int tid   = threadIdx.x;
    const int sbase = blockIdx.x * TS;

    // phase-B identity
    const int op    = tid >> 6;      // 0..3  (output pair)
    const int sl    = tid & 63;      // 0..63 (s within tile)
    const int o0    = op * 2;
    const int o1    = o0 + 1;
    const int s     = sbase + sl;

    // phase-A identity
    const int jg4   = (tid >> 5) * 4;  // j group base: 0,4,...,28
    const int ss    = tid & 31;        // 0..31

    // ---- prologue: stage-1 weights tile to SMEM ----
    for (int k = tid; k < CIN * TS; k += 256) {
        int j  = k >> 6;
        int sj = k & 63;
        w1s[j][sj] = g_w1sum[j * S_DIM + sbase + sj];
    }

    // ---- prologue: w2 tile for this thread's two output channels -> regs ----
    float w2a[CIN], w2b[CIN];
#pragma unroll
    for (int j = 0; j < CIN; ++j) {
        w2a[j] = w2[((size_t)o0 * CIN + j) * S_DIM + s];
        w2b[j] = w2[((size_t)o1 * CIN + j) * S_DIM + s];
    }
    const float bias0 = bias[o0 * S_DIM + s];
    const float bias1 = bias[o1 * S_DIM + s];
    __syncthreads();

    const int b0 = blockIdx.y * BPB;

    // ---- incremental base pointers (hoisted 64-bit math, loop adds consts) ----
    const float* xpf  = x + (size_t)b0 * CIN * S_DIM + sbase
                          + jg4 * S_DIM + ss;                  // prefetch base
    float*       outp = out + ((size_t)b0 * COUT + o0) * S_DIM + s;

    // ---- distance-2 circular prefetch buffers (slot = batch & 1) ----
    float xpa[2][4], xpc[2][4];
#pragma unroll
    for (int p = 0; p < 2; ++p) {             // preload batches b0, b0+1
        const float* xb = xpf + (size_t)p * CIN * S_DIM;
#pragma unroll
        for (int q = 0; q < 4; ++q) {
            xpa[p][q] = __ldcs(&xb[q * S_DIM]);
            xpc[p][q] = __ldcs(&xb[q * S_DIM + 32]);
        }
    }
    xpf += (size_t)2 * CIN * S_DIM;           // next batch to fetch = b0+2

#pragma unroll
    for (int bi = 0; bi < BPB; ++bi) {        // FULLY UNROLLED (BPB = 8)
        const int buf = bi & 1;               // compile-time constant per copy

        // ---- phase A: h = tanh(x * w1sum) from prefetched regs, 2x STS.128 ----
        float hv0[4], hv1[4];
#pragma unroll
        for (int q = 0; q < 4; ++q) {
            int j = jg4 + q;
            hv0[q] = tanh_fast(xpa[buf][q] * w1s[j][ss]);
            hv1[q] = tanh_fast(xpc[buf][q] * w1s[j][ss + 32]);
        }
        *(float4*)&hsh[buf][ss][jg4]      = make_float4(hv0[0], hv0[1], hv0[2], hv0[3]);
        *(float4*)&hsh[buf][ss + 32][jg4] = make_float4(hv1[0], hv1[1], hv1[2], hv1[3]);

        // ---- re-issue the just-consumed slot for batch b+2.
        //      bi is COMPILE-TIME here: guard folds, last two copies emit
        //      no prefetch at all (no clamp, no redundant LDGs). ----
        if (bi + 2 < BPB) {
#pragma unroll
            for (int q = 0; q < 4; ++q) {
                xpa[buf][q] = __ldcs(&xpf[q * S_DIM]);
                xpc[buf][q] = __ldcs(&xpf[q * S_DIM + 32]);
            }
            xpf += (size_t)CIN * S_DIM;
        }
        __syncthreads();   // the ONLY barrier per iteration: h[buf] now visible

        // ---- phase B: 32->2 contraction, 8x LDS.128, conflict-free ----
        float acc0 = bias0, acc1 = bias1;
#pragma unroll
        for (int g = 0; g < 8; ++g) {
            float4 hv = *(const float4*)&hsh[buf][sl][g * 4];
            acc0 += hv.x * w2a[g*4+0] + hv.y * w2a[g*4+1]
                  + hv.z * w2a[g*4+2] + hv.w * w2a[g*4+3];
            acc1 += hv.x * w2b[g*4+0] + hv.y * w2b[g*4+1]
                  + hv.z * w2b[g*4+2] + hv.w * w2b[g*4+3];
        }
        // accurate tanh on the final outputs; streaming stores (write-once)
        __stcs(outp,         tanhf(acc0));
        __stcs(outp + S_DIM, tanhf(acc1));
        outp += (size_t)COUT * S_DIM;
        // no trailing barrier: next iteration writes the other smem buffer
    }
}

// ---------------------------------------------------------------------------
// Launch
// ---------------------------------------------------------------------------
extern "C" void kernel_launch(void* const* d_in, const int* in_sizes, int n_in,
                              void* d_out, int out_size) {
    const float* x    = (const float*)d_in[0];   // (128, 32, 8192)
    const float* w1   = (const float*)d_in[1];   // (32, 32, 8192)
    const float* w2   = (const float*)d_in[2];   // (8, 32, 8192)
    const float* bias = (const float*)d_in[3];   // (8, 8192)
    float* out = (float*)d_out;                  // (128, 8, 8192)

    (void)in_sizes; (void)n_in; (void)out_size;

    // Kernel 1: w1 column sums (CIN*S/4 float4 elements)
    w1sum_kernel<<<(CIN * S_DIM / 4) / 256, 256>>>(w1);

    // Kernel 2: fused pipeline
    dim3 grid(S_DIM / TS, NBSPLIT);
    fused_kernel<<<grid, 256>>>(x, w2, bias, out);
}

// round 15
// speedup vs baseline: 1.1160x; 1.1160x over previous
#include <cuda_runtime.h>

#define S_DIM 8192
#define CIN   32
#define COUT  8
#define BATCH 128
#define TS    64          // s positions per block (kernel 2)
#define NBSPLIT 16        // 2048 blocks = 6.9 waves at occ-2 (tail ~8%)
#define BPB   (BATCH / NBSPLIT)
#define HPAD  36          // padded row stride for transposed h tile (floats)

static_assert(BPB % 2 == 0, "batch-pairing needs even BPB");
static_assert(BATCH % NBSPLIT == 0, "clean batch split");

// 1 MB scratch for w1sum[j][s] = sum_i w1[i][j][s]
__device__ float g_w1sum[CIN * S_DIM];

__device__ __forceinline__ float tanh_fast(float x) {
    float y;
    asm("tanh.approx.f32 %0, %1;" : "=f"(y) : "f"(x));
    return y;
}

// ---------------------------------------------------------------------------
// Kernel 1: w1sum[j,s] = sum_i w1[i,j,s].  float4, coalesced, streaming.
// ---------------------------------------------------------------------------
__global__ void w1sum_kernel(const float* __restrict__ w1) {
    int t = blockIdx.x * blockDim.x + threadIdx.x;   // over CIN*S/4 float4s
    const float4* w14 = (const float4*)w1;
    float4 acc = make_float4(0.f, 0.f, 0.f, 0.f);
#pragma unroll
    for (int i = 0; i < CIN; ++i) {
        float4 v = __ldcs(&w14[(size_t)i * (CIN * S_DIM / 4) + t]);
        acc.x += v.x; acc.y += v.y; acc.z += v.z; acc.w += v.w;
    }
    ((float4*)g_w1sum)[t] = acc;
}

// ---------------------------------------------------------------------------
// Kernel 2: fused pipeline. R13 profile: issue/latency bound at forced occ-2
// (issue 35%, DRAM 34%, 125 regs). Per-warp issue-count attack:
//  * stage-1 weights LOOP-INVARIANT per thread -> held in 8 REGISTERS;
//    w1s smem tile deleted (no per-batch LDS, no prologue barrier)
//  * tanh.approx on outputs too (rel_err ~1e-5 << 1e-3)
//  * BATCH-PAIRING: one __syncthreads per TWO batches (quad-buffered h tiles)
//  * split accumulator chains (FFMA dep depth 16)
// Bank math unchanged: STS.128/LDS.128 on the HPAD=36 tile are conflict-free.
// ---------------------------------------------------------------------------
__global__ __launch_bounds__(256, 2)
void fused_kernel(const float* __restrict__ x,
                  const float* __restrict__ w2,
                  const float* __restrict__ bias,
                  float* __restrict__ out) {
    __shared__ float hsh[4][TS][HPAD];         // QUAD-BUFFERED h tiles, 36.9 KB

    const int tid   = threadIdx.x;
    const int sbase = blockIdx.x * TS;

    // phase-B identity
    const int op    = tid >> 6;      // 0..3  (output pair)
    const int sl    = tid & 63;      // 0..63
    const int o0    = op * 2;
    const int o1    = o0 + 1;
    const int s     = sbase + sl;

    // phase-A identity
    const int jg4   = (tid >> 5) * 4;  // 0,4,...,28
    const int ss    = tid & 31;        // 0..31

    // ---- prologue: stage-1 weights -> REGISTERS (loop-invariant, coalesced) ----
    float wra[4], wrc[4];
#pragma unroll
    for (int q = 0; q < 4; ++q) {
        wra[q] = g_w1sum[(jg4 + q) * S_DIM + sbase + ss];
        wrc[q] = g_w1sum[(jg4 + q) * S_DIM + sbase + ss + 32];
    }

    // ---- prologue: w2 tile (2 output channels) -> 64 regs ----
    float w2a[CIN], w2b[CIN];
#pragma unroll
    for (int j = 0; j < CIN; ++j) {
        w2a[j] = w2[((size_t)o0 * CIN + j) * S_DIM + s];
        w2b[j] = w2[((size_t)o1 * CIN + j) * S_DIM + s];
    }
    const float bias0 = bias[o0 * S_DIM + s];
    const float bias1 = bias[o1 * S_DIM + s];
    // no prologue barrier needed: no smem written yet

    const int b0 = blockIdx.y * BPB;
    const float* xpf  = x + (size_t)b0 * CIN * S_DIM + sbase + jg4 * S_DIM + ss;
    float*       outp = out + ((size_t)b0 * COUT + o0) * S_DIM + s;

    // ---- preload x for the first batch pair (16 regs) ----
    float xa0[4], xc0[4], xa1[4], xc1[4];
#pragma unroll
    for (int q = 0; q < 4; ++q) {
        xa0[q] = __ldcs(&xpf[q * S_DIM]);
        xc0[q] = __ldcs(&xpf[q * S_DIM + 32]);
        xa1[q] = __ldcs(&xpf[(size_t)CIN * S_DIM + q * S_DIM]);
        xc1[q] = __ldcs(&xpf[(size_t)CIN * S_DIM + q * S_DIM + 32]);
    }
    xpf += (size_t)2 * CIN * S_DIM;

#pragma unroll
    for (int pi = 0; pi < BPB / 2; ++pi) {     // FULLY UNROLLED (4 pair-iters)
        const int t0 = (pi & 1) * 2;           // tile pair {t0, t0+1}, folds

        // ---- phase A: both batches of the pair -> 2 h tiles, 4x STS.128 ----
        {
            float h0[4], h1[4], h2[4], h3[4];
#pragma unroll
            for (int q = 0; q < 4; ++q) {
                h0[q] = tanh_fast(xa0[q] * wra[q]);
                h1[q] = tanh_fast(xc0[q] * wrc[q]);
                h2[q] = tanh_fast(xa1[q] * wra[q]);
                h3[q] = tanh_fast(xc1[q] * wrc[q]);
            }
            *(float4*)&hsh[t0    ][ss     ][jg4] = make_float4(h0[0], h0[1], h0[2], h0[3]);
            *(float4*)&hsh[t0    ][ss + 32][jg4] = make_float4(h1[0], h1[1], h1[2], h1[3]);
            *(float4*)&hsh[t0 + 1][ss     ][jg4] = make_float4(h2[0], h2[1], h2[2], h2[3]);
            *(float4*)&hsh[t0 + 1][ss + 32][jg4] = make_float4(h3[0], h3[1], h3[2], h3[3]);
        }

        // ---- prefetch next pair (compile-time guard: last iter emits none) ----
        if (pi + 1 < BPB / 2) {
#pragma unroll
            for (int q = 0; q < 4; ++q) {
                xa0[q] = __ldcs(&xpf[q * S_DIM]);
                xc0[q] = __ldcs(&xpf[q * S_DIM + 32]);
                xa1[q] = __ldcs(&xpf[(size_t)CIN * S_DIM + q * S_DIM]);
                xc1[q] = __ldcs(&xpf[(size_t)CIN * S_DIM + q * S_DIM + 32]);
            }
            xpf += (size_t)2 * CIN * S_DIM;
        }
        __syncthreads();   // ONE barrier per TWO batches

        // ---- phase B, batch even: split accumulator chains (depth 16) ----
        {
            float p0 = bias0, p1 = 0.f, r0 = bias1, r1 = 0.f;
#pragma unroll
            for (int g = 0; g < 4; ++g) {
                float4 hv = *(const float4*)&hsh[t0][sl][g * 4];
                p0 += hv.x * w2a[g*4+0] + hv.y * w2a[g*4+1]
                    + hv.z * w2a[g*4+2] + hv.w * w2a[g*4+3];
                r0 += hv.x * w2b[g*4+0] + hv.y * w2b[g*4+1]
                    + hv.z * w2b[g*4+2] + hv.w * w2b[g*4+3];
            }
#pragma unroll
            for (int g = 4; g < 8; ++g) {
                float4 hv = *(const float4*)&hsh[t0][sl][g * 4];
                p1 += hv.x * w2a[g*4+0] + hv.y * w2a[g*4+1]
                    + hv.z * w2a[g*4+2] + hv.w * w2a[g*4+3];
                r1 += hv.x * w2b[g*4+0] + hv.y * w2b[g*4+1]
                    + hv.z * w2b[g*4+2] + hv.w * w2b[g*4+3];
            }
            __stcs(outp,         tanh_fast(p0 + p1));   // approx output tanh
            __stcs(outp + S_DIM, tanh_fast(r0 + r1));
            outp += (size_t)COUT * S_DIM;
        }

        // ---- phase B, batch odd ----
        {
            float p0 = bias0, p1 = 0.f, r0 = bias1, r1 = 0.f;
#pragma unroll
            for (int g = 0; g < 4; ++g) {
                float4 hv = *(const float4*)&hsh[t0 + 1][sl][g * 4];
                p0 += hv.x * w2a[g*4+0] + hv.y * w2a[g*4+1]
                    + hv.z * w2a[g*4+2] + hv.w * w2a[g*4+3];
                r0 += hv.x * w2b[g*4+0] + hv.y * w2b[g*4+1]
                    + hv.z * w2b[g*4+2] + hv.w * w2b[g*4+3];
            }
#pragma unroll
            for (int g = 4; g < 8; ++g) {
                float4 hv = *(const float4*)&hsh[t0 + 1][sl][g * 4];
                p1 += hv.x * w2a[g*4+0] + hv.y * w2a[g*4+1]
                    + hv.z * w2a[g*4+2] + hv.w * w2a[g*4+3];
                r1 += hv.x * w2b[g*4+0] + hv.y * w2b[g*4+1]
                    + hv.z * w2b[g*4+2] + hv.w * w2b[g*4+3];
            }
            __stcs(outp,         tanh_fast(p0 + p1));
            __stcs(outp + S_DIM, tanh_fast(r0 + r1));
            outp += (size_t)COUT * S_DIM;
        }
        // no trailing barrier: next pair writes the OTHER two tiles; its
        // barrier orders these reads before the tiles are rewritten.
    }
}

// ---------------------------------------------------------------------------
// Launch
// ---------------------------------------------------------------------------
extern "C" void kernel_launch(void* const* d_in, const int* in_sizes, int n_in,
                              void* d_out, int out_size) {
    const float* x    = (const float*)d_in[0];   // (128, 32, 8192)
    const float* w1   = (const float*)d_in[1];   // (32, 32, 8192)
    const float* w2   = (const float*)d_in[2];   // (8, 32, 8192)
    const float* bias = (const float*)d_in[3];   // (8, 8192)
    float* out = (float*)d_out;                  // (128, 8, 8192)

    (void)in_sizes; (void)n_in; (void)out_size;

    w1sum_kernel<<<(CIN * S_DIM / 4) / 256, 256>>>(w1);

    dim3 grid(S_DIM / TS, NBSPLIT);
    fused_kernel<<<grid, 256>>>(x, w2, bias, out);
}